// round 2
// baseline (speedup 1.0000x reference)
#include <cuda_runtime.h>
#include <cuda_bf16.h>

#define BSZ   512
#define TT    200
#define HID   128
#define GG    512
#define EMBD  100
#define VOC   30000
#define NCLS  9

__device__ float g_proj[2][VOC * GG];
__device__ float g_h[2][BSZ * TT * HID];

typedef unsigned long long u64;

__device__ __forceinline__ u64 pk2(float lo, float hi) {
    u64 r; asm("mov.b64 %0, {%1,%2};" : "=l"(r) : "f"(lo), "f"(hi)); return r;
}
__device__ __forceinline__ void upk2(u64 v, float& lo, float& hi) {
    asm("mov.b64 {%0,%1}, %2;" : "=f"(lo), "=f"(hi) : "l"(v));
}
__device__ __forceinline__ u64 dup2(float x) { return pk2(x, x); }
__device__ __forceinline__ u64 fma2(u64 a, u64 b, u64 c) {
    u64 d; asm("fma.rn.f32x2 %0, %1, %2, %3;" : "=l"(d) : "l"(a), "l"(b), "l"(c)); return d;
}
__device__ __forceinline__ float sigf(float x) {
    return __fdividef(1.0f, 1.0f + __expf(-x));
}

// 16 f32x2 FMAs: 4 row-pairs x 2 columns x (k, k+1)
#define STEP2(HA,HB,HC,HD, UA0,UB0,UA1,UB1) {                  \
    u64 da0 = dup2(UA0), db0 = dup2(UB0);                      \
    u64 da1 = dup2(UA1), db1 = dup2(UB1);                      \
    a00 = fma2(HA.x, da0, a00); a00 = fma2(HA.y, db0, a00);    \
    a01 = fma2(HB.x, da0, a01); a01 = fma2(HB.y, db0, a01);    \
    a02 = fma2(HC.x, da0, a02); a02 = fma2(HC.y, db0, a02);    \
    a03 = fma2(HD.x, da0, a03); a03 = fma2(HD.y, db0, a03);    \
    a10 = fma2(HA.x, da1, a10); a10 = fma2(HA.y, db1, a10);    \
    a11 = fma2(HB.x, da1, a11); a11 = fma2(HB.y, db1, a11);    \
    a12 = fma2(HC.x, da1, a12); a12 = fma2(HC.y, db1, a12);    \
    a13 = fma2(HD.x, da1, a13); a13 = fma2(HD.y, db1, a13); }

// ---------------------------------------------------------------------------
// proj[v][j] = sum_e emb[v][e]*W[e][j] + b[j], both directions.
// grid 148 (dir = bid&1, 74 blocks/dir x 406 vocab rows), block 256.
// smem: Wsm[100*512] f32 (204800B) + epack[4*100] f32x2 (3200B)
// ---------------------------------------------------------------------------
__global__ __launch_bounds__(256, 1)
void proj_kernel(const float* __restrict__ emb,
                 const float* __restrict__ Wf, const float* __restrict__ bf,
                 const float* __restrict__ Wb, const float* __restrict__ bb)
{
    extern __shared__ char sm_raw[];
    float* Wsm = (float*)sm_raw;
    u64* epack = (u64*)(sm_raw + 204800);

    const int tid = threadIdx.x;
    const int dir = blockIdx.x & 1;
    const int blk = blockIdx.x >> 1;
    const float* W    = dir ? Wb : Wf;
    const float* bias = dir ? bb : bf;
    float* out = g_proj[dir];
    const int j0 = tid, j1 = tid + 256;

    for (int idx = tid; idx < EMBD * GG; idx += 256) Wsm[idx] = W[idx];
    const float bj0 = bias[j0], bj1 = bias[j1];
    __syncthreads();

    const int r0 = blk * 406;
    const int r1 = min(r0 + 406, VOC);

    for (int v0 = r0; v0 < r1; v0 += 8) {
        for (int idx = tid; idx < 4 * EMBD; idx += 256) {
            int p = idx / EMBD, k = idx % EMBD;
            int ra = v0 + 2 * p, rb = ra + 1;
            float ea = (ra < VOC) ? emb[ra * EMBD + k] : 0.0f;
            float eb = (rb < VOC) ? emb[rb * EMBD + k] : 0.0f;
            epack[p * EMBD + k] = pk2(ea, eb);
        }
        __syncthreads();

        u64 a00 = dup2(bj0), a01 = a00, a02 = a00, a03 = a00;
        u64 a10 = dup2(bj1), a11 = a10, a12 = a10, a13 = a10;

        #pragma unroll 5
        for (int k = 0; k < EMBD; k += 2) {
            ulonglong2 e0 = *(const ulonglong2*)&epack[k];
            ulonglong2 e1 = *(const ulonglong2*)&epack[EMBD + k];
            ulonglong2 e2 = *(const ulonglong2*)&epack[2 * EMBD + k];
            ulonglong2 e3 = *(const ulonglong2*)&epack[3 * EMBD + k];
            float wa0 = Wsm[k * GG + j0],       wa1 = Wsm[k * GG + j1];
            float wb0 = Wsm[(k + 1) * GG + j0], wb1 = Wsm[(k + 1) * GG + j1];
            STEP2(e0, e1, e2, e3, wa0, wb0, wa1, wb1);
        }
        __syncthreads();

        u64 s0[4] = {a00, a01, a02, a03};
        u64 s1[4] = {a10, a11, a12, a13};
        #pragma unroll
        for (int p = 0; p < 4; p++) {
            float o0, o1, o2, o3;
            upk2(s0[p], o0, o1);
            upk2(s1[p], o2, o3);
            int ra = v0 + 2 * p, rb = ra + 1;
            if (ra < VOC) { out[ra * GG + j0] = o0; out[ra * GG + j1] = o2; }
            if (rb < VOC) { out[rb * GG + j0] = o1; out[rb * GG + j1] = o3; }
        }
    }
}

// ---------------------------------------------------------------------------
// Persistent recurrent LSTM. grid 128 = 2 dirs x 64 chunks of 8 batch rows.
// block 256; thread owns z columns (tid, tid+256).
// smem: Usm[96*512] f32 | hpack[4*128] f32x2 | zbuf[512*4] f32x2 | tcache[8*200]
// ---------------------------------------------------------------------------
__global__ __launch_bounds__(256, 1)
void lstm_kernel(const int* __restrict__ tokens,
                 const float* __restrict__ Uf, const float* __restrict__ Ub)
{
    extern __shared__ char sm_raw[];
    float* Usm  = (float*)sm_raw;                  // 196608B
    u64* hpack  = (u64*)(sm_raw + 196608);         // 4096B
    u64* zbuf   = (u64*)(sm_raw + 200704);         // 16384B
    int* tcache = (int*)(sm_raw + 217088);         // 6400B

    const int tid = threadIdx.x;
    const int dir = blockIdx.x >> 6;
    const int b0  = (blockIdx.x & 63) * 8;
    const int j0 = tid, j1 = tid + 256;
    const float* Ug   = dir ? Ub : Uf;
    const float* proj = g_proj[dir];
    float* hout = g_h[dir];

    for (int idx = tid; idx < 96 * GG; idx += 256) Usm[idx] = Ug[idx];
    float ur0[32], ur1[32];
    #pragma unroll
    for (int i = 0; i < 32; i++) {
        ur0[i] = Ug[(96 + i) * GG + j0];
        ur1[i] = Ug[(96 + i) * GG + j1];
    }
    for (int idx = tid; idx < 8 * TT; idx += 256) {
        int r = idx / TT, t = idx % TT;
        tcache[idx] = tokens[(b0 + r) * TT + t];
    }
    hpack[tid] = 0ULL;
    hpack[tid + 256] = 0ULL;
    float cst[4] = {0.f, 0.f, 0.f, 0.f};
    __syncthreads();

    float xn0[8], xn1[8];
    {
        int t0 = dir ? (TT - 1) : 0;
        #pragma unroll
        for (int r = 0; r < 8; r++) {
            int tok = tcache[r * TT + t0];
            xn0[r] = proj[tok * GG + j0];
            xn1[r] = proj[tok * GG + j1];
        }
    }

    const int m     = tid >> 1;        // hidden unit this thread updates
    const int pb    = (tid & 1) * 2;   // first row-pair
    const int rbase = pb * 2;          // first batch row (local)

    for (int s = 0; s < TT; s++) {
        const int t = dir ? (TT - 1 - s) : s;

        u64 a00 = pk2(xn0[0], xn0[1]), a01 = pk2(xn0[2], xn0[3]);
        u64 a02 = pk2(xn0[4], xn0[5]), a03 = pk2(xn0[6], xn0[7]);
        u64 a10 = pk2(xn1[0], xn1[1]), a11 = pk2(xn1[2], xn1[3]);
        u64 a12 = pk2(xn1[4], xn1[5]), a13 = pk2(xn1[6], xn1[7]);

        // prefetch next step's xz rows (latency hidden under matmul)
        {
            int sn = (s + 1 < TT) ? (s + 1) : s;
            int tn = dir ? (TT - 1 - sn) : sn;
            #pragma unroll
            for (int r = 0; r < 8; r++) {
                int tok = tcache[r * TT + tn];
                xn0[r] = proj[tok * GG + j0];
                xn1[r] = proj[tok * GG + j1];
            }
        }

        // h @ U : smem rows 0..95
        #pragma unroll 8
        for (int k = 0; k < 96; k += 2) {
            ulonglong2 h0 = *(const ulonglong2*)&hpack[k];
            ulonglong2 h1 = *(const ulonglong2*)&hpack[128 + k];
            ulonglong2 h2 = *(const ulonglong2*)&hpack[256 + k];
            ulonglong2 h3 = *(const ulonglong2*)&hpack[384 + k];
            float ua0 = Usm[k * GG + j0],       ua1 = Usm[k * GG + j1];
            float ub0 = Usm[(k + 1) * GG + j0], ub1 = Usm[(k + 1) * GG + j1];
            STEP2(h0, h1, h2, h3, ua0, ub0, ua1, ub1);
        }
        // register rows 96..127
        #pragma unroll
        for (int kk = 0; kk < 32; kk += 2) {
            const int k = 96 + kk;
            ulonglong2 h0 = *(const ulonglong2*)&hpack[k];
            ulonglong2 h1 = *(const ulonglong2*)&hpack[128 + k];
            ulonglong2 h2 = *(const ulonglong2*)&hpack[256 + k];
            ulonglong2 h3 = *(const ulonglong2*)&hpack[384 + k];
            STEP2(h0, h1, h2, h3, ur0[kk], ur0[kk + 1], ur1[kk], ur1[kk + 1]);
        }

        // publish z
        zbuf[j0 * 4 + 0] = a00; zbuf[j0 * 4 + 1] = a01;
        zbuf[j0 * 4 + 2] = a02; zbuf[j0 * 4 + 3] = a03;
        zbuf[j1 * 4 + 0] = a10; zbuf[j1 * 4 + 1] = a11;
        zbuf[j1 * 4 + 2] = a12; zbuf[j1 * 4 + 3] = a13;
        __syncthreads();

        // gate epilogue: thread owns hidden m, 4 batch rows (pairs pb, pb+1)
        {
            u64 zi0 = zbuf[m * 4 + pb],         zi1 = zbuf[m * 4 + pb + 1];
            u64 zf0 = zbuf[(128 + m) * 4 + pb], zf1 = zbuf[(128 + m) * 4 + pb + 1];
            u64 zg0 = zbuf[(256 + m) * 4 + pb], zg1 = zbuf[(256 + m) * 4 + pb + 1];
            u64 zo0 = zbuf[(384 + m) * 4 + pb], zo1 = zbuf[(384 + m) * 4 + pb + 1];
            float zi[4], zf[4], zg[4], zo[4], hv[4];
            upk2(zi0, zi[0], zi[1]); upk2(zi1, zi[2], zi[3]);
            upk2(zf0, zf[0], zf[1]); upk2(zf1, zf[2], zf[3]);
            upk2(zg0, zg[0], zg[1]); upk2(zg1, zg[2], zg[3]);
            upk2(zo0, zo[0], zo[1]); upk2(zo1, zo[2], zo[3]);
            #pragma unroll
            for (int r = 0; r < 4; r++) {
                float ii = sigf(zi[r]);
                float ff = sigf(zf[r]);
                float gg = fmaxf(zg[r], 0.0f);
                float oo = sigf(zo[r]);
                float c  = ff * cst[r] + ii * gg;
                cst[r] = c;
                hv[r] = oo * fmaxf(c, 0.0f);
                hout[((size_t)(b0 + rbase + r) * TT + t) * HID + m] = hv[r];
            }
            hpack[pb * 128 + m]       = pk2(hv[0], hv[1]);
            hpack[(pb + 1) * 128 + m] = pk2(hv[2], hv[3]);
        }
        __syncthreads();
    }
}

// ---------------------------------------------------------------------------
// BN + dense(256->9) + softmax. One warp per (b,t). block 256 = 8 positions.
// ---------------------------------------------------------------------------
__global__ __launch_bounds__(256, 4)
void head_kernel(const float* __restrict__ gamma, const float* __restrict__ beta,
                 const float* __restrict__ mean,  const float* __restrict__ var,
                 const float* __restrict__ Wd,    const float* __restrict__ bd,
                 float* __restrict__ out)
{
    __shared__ float scale[2 * HID], shift[2 * HID];
    __shared__ float Wsm[2 * HID * NCLS];
    __shared__ float bsm[NCLS];

    const int tid = threadIdx.x;
    {
        int d = tid;
        float rs = rsqrtf(var[d] + 1e-3f);
        float sc = rs * gamma[d];
        scale[d] = sc;
        shift[d] = beta[d] - mean[d] * sc;
        #pragma unroll
        for (int c = 0; c < NCLS; c++) Wsm[d * NCLS + c] = Wd[d * NCLS + c];
        if (tid < NCLS) bsm[tid] = bd[tid];
    }
    __syncthreads();

    const int wid  = tid >> 5;
    const int lane = tid & 31;
    const int pos  = blockIdx.x * 8 + wid;   // pos = b*TT + t
    const int d0 = lane * 4;
    const int d1 = 128 + lane * 4;

    float4 hf = *(const float4*)&g_h[0][(size_t)pos * HID + d0];
    float4 hb = *(const float4*)&g_h[1][(size_t)pos * HID + d0];
    float v[8];
    v[0] = hf.x * scale[d0]     + shift[d0];
    v[1] = hf.y * scale[d0 + 1] + shift[d0 + 1];
    v[2] = hf.z * scale[d0 + 2] + shift[d0 + 2];
    v[3] = hf.w * scale[d0 + 3] + shift[d0 + 3];
    v[4] = hb.x * scale[d1]     + shift[d1];
    v[5] = hb.y * scale[d1 + 1] + shift[d1 + 1];
    v[6] = hb.z * scale[d1 + 2] + shift[d1 + 2];
    v[7] = hb.w * scale[d1 + 3] + shift[d1 + 3];

    float acc[NCLS];
    #pragma unroll
    for (int c = 0; c < NCLS; c++) acc[c] = 0.0f;
    #pragma unroll
    for (int i = 0; i < 8; i++) {
        int d = (i < 4) ? (d0 + i) : (d1 + i - 4);
        #pragma unroll
        for (int c = 0; c < NCLS; c++) acc[c] += v[i] * Wsm[d * NCLS + c];
    }
    #pragma unroll
    for (int off = 16; off >= 1; off >>= 1) {
        #pragma unroll
        for (int c = 0; c < NCLS; c++)
            acc[c] += __shfl_xor_sync(0xFFFFFFFFu, acc[c], off);
    }

    if (lane == 0) {
        float z[NCLS], mx = -1e30f;
        #pragma unroll
        for (int c = 0; c < NCLS; c++) { z[c] = acc[c] + bsm[c]; mx = fmaxf(mx, z[c]); }
        float sum = 0.0f;
        #pragma unroll
        for (int c = 0; c < NCLS; c++) { z[c] = __expf(z[c] - mx); sum += z[c]; }
        float inv = __fdividef(1.0f, sum);
        #pragma unroll
        for (int c = 0; c < NCLS; c++) out[(size_t)pos * NCLS + c] = z[c] * inv;
    }
}

extern "C" void kernel_launch(void* const* d_in, const int* in_sizes, int n_in,
                              void* d_out, int out_size)
{
    const int*   tokens = (const int*)d_in[0];
    const float* emb    = (const float*)d_in[1];
    const float* Wf     = (const float*)d_in[2];
    const float* Uf     = (const float*)d_in[3];
    const float* bf     = (const float*)d_in[4];
    const float* Wb     = (const float*)d_in[5];
    const float* Ub     = (const float*)d_in[6];
    const float* bb     = (const float*)d_in[7];
    const float* gamma  = (const float*)d_in[8];
    const float* beta   = (const float*)d_in[9];
    const float* mmean  = (const float*)d_in[10];
    const float* mvar   = (const float*)d_in[11];
    const float* Wd     = (const float*)d_in[12];
    const float* bd     = (const float*)d_in[13];
    float* out = (float*)d_out;

    static bool attr_done = false;
    if (!attr_done) {
        cudaFuncSetAttribute(proj_kernel, cudaFuncAttributeMaxDynamicSharedMemorySize, 208000);
        cudaFuncSetAttribute(lstm_kernel, cudaFuncAttributeMaxDynamicSharedMemorySize, 223488);
        attr_done = true;
    }

    proj_kernel<<<148, 256, 208000>>>(emb, Wf, bf, Wb, bb);
    lstm_kernel<<<128, 256, 223488>>>(tokens, Uf, Ub);
    head_kernel<<<BSZ * TT / 8, 256>>>(gamma, beta, mmean, mvar, Wd, bd, out);
}